// round 16
// baseline (speedup 1.0000x reference)
#include <cuda_runtime.h>
#include <cuda_fp16.h>
#include <cstdint>
#include <math.h>

#define B_   4
#define S_   4096
#define D_   512
#define H_   8
#define KD_  64
#define R_   256
#define M_   (B_*S_)
#define ROWS_ (M_*H_)
#define EPS_ 1e-3f
#define SCALE_ 0.125f
#define NSPLIT 16

// ---- mma.sync / ldmatrix / cp.async helpers ----
__device__ __forceinline__ uint32_t smem_u32(const void* p) {
    uint32_t a;
    asm("{ .reg .u64 t; cvta.to.shared.u64 t, %1; cvt.u32.u64 %0, t; }" : "=r"(a) : "l"(p));
    return a;
}
__device__ __forceinline__ void ldsm4(uint32_t& r0, uint32_t& r1, uint32_t& r2, uint32_t& r3,
                                      uint32_t addr) {
    asm volatile("ldmatrix.sync.aligned.m8n8.x4.shared.b16 {%0,%1,%2,%3}, [%4];"
                 : "=r"(r0), "=r"(r1), "=r"(r2), "=r"(r3) : "r"(addr));
}
__device__ __forceinline__ void ldsm4t(uint32_t& r0, uint32_t& r1, uint32_t& r2, uint32_t& r3,
                                       uint32_t addr) {
    asm volatile("ldmatrix.sync.aligned.m8n8.x4.trans.shared.b16 {%0,%1,%2,%3}, [%4];"
                 : "=r"(r0), "=r"(r1), "=r"(r2), "=r"(r3) : "r"(addr));
}
// fp16 x fp16 -> f32 accum
__device__ __forceinline__ void mma16816(float* c, const uint32_t* a, const uint32_t* b) {
    asm volatile("mma.sync.aligned.m16n8k16.row.col.f32.f16.f16.f32 "
                 "{%0,%1,%2,%3}, {%4,%5,%6,%7}, {%8,%9}, {%0,%1,%2,%3};"
                 : "+f"(c[0]), "+f"(c[1]), "+f"(c[2]), "+f"(c[3])
                 : "r"(a[0]), "r"(a[1]), "r"(a[2]), "r"(a[3]), "r"(b[0]), "r"(b[1]));
}
// fp16 x fp16 -> f16 accum (2x rate)
__device__ __forceinline__ void mma16816h(uint32_t* c, const uint32_t* a, const uint32_t* b) {
    asm volatile("mma.sync.aligned.m16n8k16.row.col.f16.f16.f16.f16 "
                 "{%0,%1}, {%2,%3,%4,%5}, {%6,%7}, {%0,%1};"
                 : "+r"(c[0]), "+r"(c[1])
                 : "r"(a[0]), "r"(a[1]), "r"(a[2]), "r"(a[3]), "r"(b[0]), "r"(b[1]));
}
__device__ __forceinline__ void cpa16(uint32_t dst, const void* src) {
    asm volatile("cp.async.cg.shared.global [%0], [%1], 16;" :: "r"(dst), "l"(src));
}
#define CPA_COMMIT() asm volatile("cp.async.commit_group;" ::: "memory")
#define CPA_WAIT(n)  asm volatile("cp.async.wait_group %0;" :: "n"(n) : "memory")

__device__ __forceinline__ void split_f16(float v, __half& h, __half& l) {
    h = __float2half_rn(v);
    l = __float2half_rn(v - __half2float(h));
}

// ---------------- scratch ----------------
__device__ __half g_vh[M_*D_];
__device__ __half g_vl[M_*D_];
__device__ __half g_kfh[(size_t)ROWS_*R_];
__device__ __half g_kfl[(size_t)ROWS_*R_];
__device__ float g_kvp2[(size_t)B_*H_*NSPLIT*80*R_];
__device__ __half g_qfh[(size_t)ROWS_*R_];
__device__ __half g_qfl[(size_t)ROWS_*R_];
__device__ __half g_kvth[B_*H_*80*R_];
__device__ __half g_kvtl[B_*H_*80*R_];
__device__ __half g_xh[M_*D_];
__device__ __half g_xl[M_*D_];
__device__ __half g_ah[M_*D_];
__device__ __half g_al[M_*D_];
__device__ __half g_qh[M_*D_];
__device__ __half g_ql[M_*D_];
__device__ __half g_kh[M_*D_];
__device__ __half g_kl[M_*D_];
__device__ __half g_rfh[R_*KD_];
__device__ __half g_rfl[R_*KD_];
__device__ __half g_wh[4][D_*D_];
__device__ __half g_wl[4][D_*D_];

// ---------------- fp32 -> fp16 hi/lo split ----------------
__global__ void split_kernel(const float4* __restrict__ src,
                             uint2* __restrict__ hi, uint2* __restrict__ lo) {
    int i = blockIdx.x*256 + threadIdx.x;
    float4 v = src[i];
    __half h0,h1,h2,h3,l0,l1,l2,l3;
    split_f16(v.x,h0,l0); split_f16(v.y,h1,l1);
    split_f16(v.z,h2,l2); split_f16(v.w,h3,l3);
    __half2 hp0 = __halves2half2(h0,h1), hp1 = __halves2half2(h2,h3);
    __half2 lp0 = __halves2half2(l0,l1), lp1 = __halves2half2(l2,l3);
    hi[i] = make_uint2(*(uint32_t*)&hp0, *(uint32_t*)&hp1);
    lo[i] = make_uint2(*(uint32_t*)&lp0, *(uint32_t*)&lp1);
}

// ---------------- all 4 weights: W[k][n] -> Wt[n][k] fp16 hi/lo ----------------
__global__ void wsplit_all(const float* __restrict__ W0, const float* __restrict__ W1,
                           const float* __restrict__ W2, const float* __restrict__ W3,
                           __half* __restrict__ Th, __half* __restrict__ Tl) {
    __shared__ float tile[32][33];
    int z = blockIdx.z;
    const float* W = (z == 0) ? W0 : (z == 1) ? W1 : (z == 2) ? W2 : W3;
    __half* th = Th + (size_t)z*D_*D_;
    __half* tl = Tl + (size_t)z*D_*D_;
    int n0 = blockIdx.x*32, k0 = blockIdx.y*32;
    int tx = threadIdx.x, ty = threadIdx.y;
    #pragma unroll
    for (int j = 0; j < 32; j += 8)
        tile[ty+j][tx] = W[(size_t)(k0+ty+j)*D_ + n0+tx];
    __syncthreads();
    #pragma unroll
    for (int j = 0; j < 32; j += 8) {
        float v = tile[tx][ty+j];
        __half h, l; split_f16(v, h, l);
        th[(size_t)(n0+ty+j)*D_ + k0+tx] = h;
        tl[(size_t)(n0+ty+j)*D_ + k0+tx] = l;
    }
}

// ============== shared tiling constants ==============
#define AST 72
#define AST2 40
#define T32_BYTES (128*AST2*2)
#define BUF32  (4*T32_BYTES)
#define MMSM (2*BUF32)

// ============== core mixed-accum mainloop body (qkv/out): ======================
// pass1 Ah*Bh -> f32 acc (1x rate); pass2 Ah*Bl, pass3 Al*Bh -> f16 accL (2x rate)
#define GEMM_CHUNK_BODY(sAh_b, sAl_b, sBh_b, sBl_b)                                   \
    _Pragma("unroll")                                                                 \
    for (int k16 = 0; k16 < 2; k16++) {                                               \
        int ak = k16*16 + a_col8;                                                     \
        int bk = k16*16 + b_col8;                                                     \
        uint32_t aF[2][4];                                                            \
        _Pragma("unroll")                                                             \
        for (int mt = 0; mt < 2; mt++)                                                \
            ldsm4(aF[mt][0], aF[mt][1], aF[mt][2], aF[mt][3],                         \
                  sAh_b + (uint32_t)((a_row + mt*16)*AST2 + ak)*2);                   \
        _Pragma("unroll")                                                             \
        for (int p = 0; p < 4; p++) {                                                 \
            uint32_t r0, r1, r2, r3;                                                  \
            ldsm4(r0, r1, r2, r3, sBh_b + (uint32_t)((b_row + p*16)*AST2 + bk)*2);    \
            uint32_t bf0[2] = {r0, r1}, bf1[2] = {r2, r3};                            \
            _Pragma("unroll")                                                         \
            for (int mt = 0; mt < 2; mt++) {                                          \
                mma16816(acc[mt][2*p],   aF[mt], bf0);                                \
                mma16816(acc[mt][2*p+1], aF[mt], bf1);                                \
            }                                                                         \
        }                                                                             \
        _Pragma("unroll")                                                             \
        for (int p = 0; p < 4; p++) {                                                 \
            uint32_t r0, r1, r2, r3;                                                  \
            ldsm4(r0, r1, r2, r3, sBl_b + (uint32_t)((b_row + p*16)*AST2 + bk)*2);    \
            uint32_t bf0[2] = {r0, r1}, bf1[2] = {r2, r3};                            \
            _Pragma("unroll")                                                         \
            for (int mt = 0; mt < 2; mt++) {                                          \
                mma16816h(accL[mt][2*p],   aF[mt], bf0);                              \
                mma16816h(accL[mt][2*p+1], aF[mt], bf1);                              \
            }                                                                         \
        }                                                                             \
        _Pragma("unroll")                                                             \
        for (int mt = 0; mt < 2; mt++)                                                \
            ldsm4(aF[mt][0], aF[mt][1], aF[mt][2], aF[mt][3],                         \
                  sAl_b + (uint32_t)((a_row + mt*16)*AST2 + ak)*2);                   \
        _Pragma("unroll")                                                             \
        for (int p = 0; p < 4; p++) {                                                 \
            uint32_t r0, r1, r2, r3;                                                  \
            ldsm4(r0, r1, r2, r3, sBh_b + (uint32_t)((b_row + p*16)*AST2 + bk)*2);    \
            uint32_t bf0[2] = {r0, r1}, bf1[2] = {r2, r3};                            \
            _Pragma("unroll")                                                         \
            for (int mt = 0; mt < 2; mt++) {                                          \
                mma16816h(accL[mt][2*p],   aF[mt], bf0);                              \
                mma16816h(accL[mt][2*p+1], aF[mt], bf1);                              \
            }                                                                         \
        }                                                                             \
    }

// fold f16 lo-accumulator into f32 (same thread-element layout)
__device__ __forceinline__ void fold_lo(float* a, const uint32_t* cl2) {
    __half2 c0 = *(const __half2*)&cl2[0];
    __half2 c1 = *(const __half2*)&cl2[1];
    a[0] += __half2float(__low2half(c0));
    a[1] += __half2float(__high2half(c0));
    a[2] += __half2float(__low2half(c1));
    a[3] += __half2float(__high2half(c1));
}

// ---------------- fused QKV GEMM: z selects weight + output (all fp16 hi/lo) ----------
__global__ void __launch_bounds__(256, 2) qkv_gemm(
        const __half* __restrict__ Ah_g, const __half* __restrict__ Al_g,
        const __half* __restrict__ Wh_g, const __half* __restrict__ Wl_g,
        __half* __restrict__ Qh, __half* __restrict__ Ql,
        __half* __restrict__ Kh, __half* __restrict__ Kl,
        __half* __restrict__ Vh, __half* __restrict__ Vl) {
    extern __shared__ __half sm[];
    uint32_t sbase = smem_u32(sm);
    int t = threadIdx.x, lane = t & 31, w = t >> 5;
    int wm = w & 3, wn = w >> 2;
    int z = blockIdx.z;
    int n0 = blockIdx.x * 128;
    size_t m0 = (size_t)blockIdx.y * 128;
    const __half* Bh_g = Wh_g + (size_t)z*D_*D_;
    const __half* Bl_g = Wl_g + (size_t)z*D_*D_;

    float acc[2][8][4] = {};
    uint32_t accL[2][8][2] = {};

    int a_row = wm*32 + (lane & 15);
    int a_col8 = (lane >> 4) * 8;
    int b_row = wn*64 + ((lane >> 4) & 1)*8 + (lane & 7);
    int b_col8 = ((lane >> 3) & 1) * 8;

    int srow[2], sc8[2];
    #pragma unroll
    for (int j = 0; j < 2; j++) { int idx = t + j*256; srow[j] = idx >> 2; sc8[j] = idx & 3; }

    auto stage = [&](int kb, uint32_t bb) {
        #pragma unroll
        for (int j = 0; j < 2; j++) {
            uint32_t off = (uint32_t)(srow[j]*AST2 + sc8[j]*8)*2;
            cpa16(bb + 0*T32_BYTES + off, Ah_g + (m0+srow[j])*D_ + kb + sc8[j]*8);
            cpa16(bb + 1*T32_BYTES + off, Al_g + (m0+srow[j])*D_ + kb + sc8[j]*8);
            cpa16(bb + 2*T32_BYTES + off, Bh_g + (size_t)(n0+srow[j])*D_ + kb + sc8[j]*8);
            cpa16(bb + 3*T32_BYTES + off, Bl_g + (size_t)(n0+srow[j])*D_ + kb + sc8[j]*8);
        }
        CPA_COMMIT();
    };

    stage(0, sbase);
    for (int c = 0; c < 16; c++) {
        int buf = c & 1;
        CPA_WAIT(0);
        __syncthreads();
        if (c < 15) stage((c+1)*32, sbase + (buf^1)*BUF32);

        uint32_t bb = sbase + buf*BUF32;
        uint32_t sAh_b = bb, sAl_b = bb + T32_BYTES;
        uint32_t sBh_b = bb + 2*T32_BYTES, sBl_b = bb + 3*T32_BYTES;
        GEMM_CHUNK_BODY(sAh_b, sAl_b, sBh_b, sBl_b)
    }

    int g = lane >> 2;
    int cl = (lane & 3) * 2;
    __half* Ch = (z == 0) ? Qh : (z == 1) ? Kh : Vh;
    __half* Cl = (z == 0) ? Ql : (z == 1) ? Kl : Vl;
    #pragma unroll
    for (int mt = 0; mt < 2; mt++)
        #pragma unroll
        for (int nt = 0; nt < 8; nt++) {
            fold_lo(acc[mt][nt], accL[mt][nt]);
            int col = n0 + wn*64 + nt*8 + cl;
            size_t r0 = m0 + wm*32 + mt*16 + g;
            #pragma unroll
            for (int half_ = 0; half_ < 2; half_++) {
                __half hx, lx, hy, ly;
                split_f16(acc[mt][nt][2*half_],   hx, lx);
                split_f16(acc[mt][nt][2*half_+1], hy, ly);
                __half2 hp = __halves2half2(hx, hy);
                __half2 lp = __halves2half2(lx, ly);
                size_t rr = r0 + half_*8;
                *(uint32_t*)(Ch + rr*D_ + col) = *(uint32_t*)&hp;
                *(uint32_t*)(Cl + rr*D_ + col) = *(uint32_t*)&lp;
            }
        }
}

// ---------------- final GEMM (fp32 out + bias) ----------------
__global__ void __launch_bounds__(256, 2) out_gemm(
        const __half* __restrict__ Ah_g, const __half* __restrict__ Al_g,
        const __half* __restrict__ Bh_g, const __half* __restrict__ Bl_g,
        float* __restrict__ C, const float* __restrict__ bias) {
    extern __shared__ __half sm[];
    uint32_t sbase = smem_u32(sm);
    int t = threadIdx.x, lane = t & 31, w = t >> 5;
    int wm = w & 3, wn = w >> 2;
    int n0 = blockIdx.x * 128;
    size_t m0 = (size_t)blockIdx.y * 128;

    float acc[2][8][4] = {};
    uint32_t accL[2][8][2] = {};

    int a_row = wm*32 + (lane & 15);
    int a_col8 = (lane >> 4) * 8;
    int b_row = wn*64 + ((lane >> 4) & 1)*8 + (lane & 7);
    int b_col8 = ((lane >> 3) & 1) * 8;

    int srow[2], sc8[2];
    #pragma unroll
    for (int j = 0; j < 2; j++) { int idx = t + j*256; srow[j] = idx >> 2; sc8[j] = idx & 3; }

    auto stage = [&](int kb, uint32_t bb) {
        #pragma unroll
        for (int j = 0; j < 2; j++) {
            uint32_t off = (uint32_t)(srow[j]*AST2 + sc8[j]*8)*2;
            cpa16(bb + 0*T32_BYTES + off, Ah_g + (m0+srow[j])*D_ + kb + sc8[j]*8);
            cpa16(bb + 1*T32_BYTES + off, Al_g + (m0+srow[j])*D_ + kb + sc8[j]*8);
            cpa16(bb + 2*T32_BYTES + off, Bh_g + (size_t)(n0+srow[j])*D_ + kb + sc8[j]*8);
            cpa16(bb + 3*T32_BYTES + off, Bl_g + (size_t)(n0+srow[j])*D_ + kb + sc8[j]*8);
        }
        CPA_COMMIT();
    };

    stage(0, sbase);
    for (int c = 0; c < 16; c++) {
        int buf = c & 1;
        CPA_WAIT(0);
        __syncthreads();
        if (c < 15) stage((c+1)*32, sbase + (buf^1)*BUF32);

        uint32_t bb = sbase + buf*BUF32;
        uint32_t sAh_b = bb, sAl_b = bb + T32_BYTES;
        uint32_t sBh_b = bb + 2*T32_BYTES, sBl_b = bb + 3*T32_BYTES;
        GEMM_CHUNK_BODY(sAh_b, sAl_b, sBh_b, sBl_b)
    }

    int g = lane >> 2;
    int cl = (lane & 3) * 2;
    #pragma unroll
    for (int mt = 0; mt < 2; mt++) {
        #pragma unroll
        for (int nt = 0; nt < 8; nt++) {
            fold_lo(acc[mt][nt], accL[mt][nt]);
            int col = n0 + wn*64 + nt*8 + cl;
            size_t r0 = m0 + wm*32 + mt*16 + g;
            float bx = bias[col], by = bias[col+1];
            *(float2*)(C + r0*D_ + col)       = make_float2(acc[mt][nt][0] + bx, acc[mt][nt][1] + by);
            *(float2*)(C + (r0 + 8)*D_ + col) = make_float2(acc[mt][nt][2] + bx, acc[mt][nt][3] + by);
        }
    }
}

// ---------------- fused feat via HMMA: z=0 -> qf, z=1 -> kf (fp16 hi/lo out) ----------
#define FSM_A (128*AST*2)
#define FSM_B (256*AST*2)
#define FSM_TOT (2*FSM_A + 2*FSM_B)
__global__ void __launch_bounds__(256) feat_mma(
        const __half* __restrict__ qh, const __half* __restrict__ ql,
        const __half* __restrict__ kh, const __half* __restrict__ kl,
        const __half* __restrict__ rfh, const __half* __restrict__ rfl,
        __half* __restrict__ qfh, __half* __restrict__ qfl,
        __half* __restrict__ kfh, __half* __restrict__ kfl) {
    extern __shared__ __half sm[];
    uint32_t sbase = smem_u32(sm);
    uint32_t sAh_b = sbase, sAl_b = sbase + FSM_A;
    uint32_t sBh_b = sbase + 2*FSM_A, sBl_b = sbase + 2*FSM_A + FSM_B;
    int t = threadIdx.x, lane = t & 31, w = t >> 5;
    int z = blockIdx.y;
    const __half* Ah_g = z ? kh : qh;
    const __half* Al_g = z ? kl : ql;
    __half* outH = z ? kfh : qfh;
    __half* outL = z ? kfl : qfl;
    size_t m0 = (size_t)blockIdx.x * 128;

    #pragma unroll
    for (int j = 0; j < 4; j++) {
        int idx = t + j*256;
        int row = idx >> 3, c8 = idx & 7;
        uint32_t off = (uint32_t)(row*AST + c8*8)*2;
        cpa16(sAh_b + off, Ah_g + (m0+row)*KD_ + c8*8);
        cpa16(sAl_b + off, Al_g + (m0+row)*KD_ + c8*8);
    }
    #pragma unroll
    for (int j = 0; j < 8; j++) {
        int idx = t + j*256;
        int row = idx >> 3, c8 = idx & 7;
        uint32_t off = (uint32_t)(row*AST + c8*8)*2;
        cpa16(sBh_b + off, rfh + row*KD_ + c8*8);
        cpa16(sBl_b + off, rfl + row*KD_ + c8*8);
    }
    CPA_COMMIT();
    CPA_WAIT(0);
    __syncthreads();

    float acc[32][4] = {};
    int a_row = w*16 + (lane & 15);
    int a_col8 = (lane >> 4) * 8;
    int b_row = ((lane >> 4) & 1)*8 + (lane & 7);
    int b_col8 = ((lane >> 3) & 1) * 8;

    #pragma unroll
    for (int k16 = 0; k16 < 4; k16++) {
        uint32_t aF[4];
        uint32_t aoff = (uint32_t)(a_row*AST + k16*16 + a_col8)*2;
        ldsm4(aF[0], aF[1], aF[2], aF[3], sAh_b + aoff);
        #pragma unroll
        for (int bs = 0; bs < 2; bs++) {
            uint32_t bBase = bs ? sBl_b : sBh_b;
            #pragma unroll
            for (int p = 0; p < 16; p++) {
                uint32_t r0, r1, r2, r3;
                ldsm4(r0, r1, r2, r3,
                      bBase + (uint32_t)((p*16 + b_row)*AST + k16*16 + b_col8)*2);
                uint32_t bf0[2] = {r0, r1}, bf1[2] = {r2, r3};
                mma16816(acc[2*p],   aF, bf0);
                mma16816(acc[2*p+1], aF, bf1);
            }
        }
        ldsm4(aF[0], aF[1], aF[2], aF[3], sAl_b + aoff);
        #pragma unroll
        for (int p = 0; p < 16; p++) {
            uint32_t r0, r1, r2, r3;
            ldsm4(r0, r1, r2, r3,
                  sBh_b + (uint32_t)((p*16 + b_row)*AST + k16*16 + b_col8)*2);
            uint32_t bf0[2] = {r0, r1}, bf1[2] = {r2, r3};
            mma16816(acc[2*p],   aF, bf0);
            mma16816(acc[2*p+1], aF, bf1);
        }
    }

    int g = lane >> 2;
    float mx0 = -1e30f, mx1 = -1e30f;
    #pragma unroll
    for (int nt = 0; nt < 32; nt++) {
        acc[nt][0] *= SCALE_; acc[nt][1] *= SCALE_;
        acc[nt][2] *= SCALE_; acc[nt][3] *= SCALE_;
        mx0 = fmaxf(mx0, fmaxf(acc[nt][0], acc[nt][1]));
        mx1 = fmaxf(mx1, fmaxf(acc[nt][2], acc[nt][3]));
    }
    mx0 = fmaxf(mx0, __shfl_xor_sync(0xffffffffu, mx0, 1));
    mx0 = fmaxf(mx0, __shfl_xor_sync(0xffffffffu, mx0, 2));
    mx1 = fmaxf(mx1, __shfl_xor_sync(0xffffffffu, mx1, 1));
    mx1 = fmaxf(mx1, __shfl_xor_sync(0xffffffffu, mx1, 2));

    size_t row0 = m0 + w*16 + g;
    int cl = (lane & 3) * 2;
    #pragma unroll
    for (int nt = 0; nt < 32; nt++) {
        int col = nt*8 + cl;
        float v0 = __expf(acc[nt][0]-mx0)+EPS_, v1 = __expf(acc[nt][1]-mx0)+EPS_;
        float v2 = __expf(acc[nt][2]-mx1)+EPS_, v3 = __expf(acc[nt][3]-mx1)+EPS_;
        __half h0,l0,h1,l1,h2,l2,h3,l3;
        split_f16(v0,h0,l0); split_f16(v1,h1,l1);
        split_f16(v2,h2,l2); split_f16(v3,h3,l3);
        __half2 hp0 = __halves2half2(h0,h1), lp0 = __halves2half2(l0,l1);
        __half2 hp1 = __halves2half2(h2,h3), lp1 = __halves2half2(l2,l3);
        *(uint32_t*)(outH + row0*R_ + col)     = *(uint32_t*)&hp0;
        *(uint32_t*)(outL + row0*R_ + col)     = *(uint32_t*)&lp0;
        *(uint32_t*)(outH + (row0+8)*R_ + col) = *(uint32_t*)&hp1;
        *(uint32_t*)(outL + (row0+8)*R_ + col) = *(uint32_t*)&lp1;
    }
}

// ---------------- kvsum via HMMA (trans ldmatrix): partials [bh][sp][80][256] ---------
#define KAST 88
#define KBST 264
#define KVS_A_T (32*KAST*2)
#define KVS_B_T (32*KBST*2)
#define KVS_BUF (2*KVS_A_T + 2*KVS_B_T)
#define KVSM (2*KVS_BUF)
__global__ void __launch_bounds__(256, 2) kvsum_mma(
        const __half* __restrict__ vh, const __half* __restrict__ vl,
        const __half* __restrict__ kfh, const __half* __restrict__ kfl,
        float* __restrict__ kvp2) {
    extern __shared__ __half sm[];
    uint32_t sbase = smem_u32(sm);
    int t = threadIdx.x, lane = t & 31, w = t >> 5;
    int sp = blockIdx.x, bh = blockIdx.y;
    int b = bh >> 3, h = bh & 7;
    int sb0 = sp * 256;

    for (int i = t; i < 512; i += 256) {
        int row = i >> 4, c = 64 + (i & 15);
        __half hv = (c == 64) ? __float2half(1.0f) : __float2half(0.0f);
        __half zv = __float2half(0.0f);
        #pragma unroll
        for (int bu = 0; bu < 2; bu++) {
            sm[(bu*KVS_BUF)/2 + row*KAST + c] = hv;
            sm[(bu*KVS_BUF + KVS_A_T)/2 + row*KAST + c] = zv;
        }
    }

    float acc[20][4] = {};
    int n0w = w * 32;

    auto stage = [&](int c, uint32_t bb) {
        int srow = t >> 3, sc8 = t & 7;
        size_t vs = (size_t)(b*S_ + sb0 + c*32 + srow)*D_ + h*KD_ + sc8*8;
        uint32_t aoff = (uint32_t)(srow*KAST + sc8*8)*2;
        cpa16(bb + aoff,           vh + vs);
        cpa16(bb + KVS_A_T + aoff, vl + vs);
        #pragma unroll
        for (int j = 0; j < 4; j++) {
            int idx = t + j*256;
            int row = idx >> 5, c8 = idx & 31;
            size_t ks = ((size_t)(b*S_ + sb0 + c*32 + row)*H_ + h)*R_ + c8*8;
            uint32_t boff = (uint32_t)(row*KBST + c8*8)*2;
            cpa16(bb + 2*KVS_A_T + boff,           kfh + ks);
            cpa16(bb + 2*KVS_A_T + KVS_B_T + boff, kfl + ks);
        }
        CPA_COMMIT();
    };

    stage(0, sbase);
    for (int c = 0; c < 8; c++) {
        int buf = c & 1;
        CPA_WAIT(0);
        __syncthreads();
        if (c < 7) stage(c+1, sbase + (buf^1)*KVS_BUF);

        uint32_t bb = sbase + buf*KVS_BUF;
        uint32_t sAh_b = bb, sAl_b = bb + KVS_A_T;
        uint32_t sBh_b = bb + 2*KVS_A_T, sBl_b = bb + 2*KVS_A_T + KVS_B_T;

        int a_k = ((lane >> 4) & 1)*8 + (lane & 7);
        int a_m8 = ((lane >> 3) & 1)*8;
        int b_k = ((lane >> 3) & 1)*8 + (lane & 7);
        int b_n8 = ((lane >> 4) & 1)*8;

        #pragma unroll
        for (int k16 = 0; k16 < 2; k16++) {
            int ks = k16*16;
            uint32_t aF[5][4];
            #pragma unroll
            for (int mi = 0; mi < 5; mi++)
                ldsm4t(aF[mi][0], aF[mi][1], aF[mi][2], aF[mi][3],
                       sAh_b + (uint32_t)((ks + a_k)*KAST + mi*16 + a_m8)*2);
            #pragma unroll
            for (int bs = 0; bs < 2; bs++) {
                uint32_t bBase = bs ? sBl_b : sBh_b;
                #pragma unroll
                for (int nb = 0; nb < 2; nb++) {
                    uint32_t r0, r1, r2, r3;
                    ldsm4t(r0, r1, r2, r3,
                           bBase + (uint32_t)((ks + b_k)*KBST + n0w + nb*16 + b_n8)*2);
                    uint32_t bf0[2] = {r0, r1}, bf1[2] = {r2, r3};
                    #pragma unroll
                    for (int mi = 0; mi < 5; mi++) {
                        mma16816(acc[mi*4 + nb*2],     aF[mi], bf0);
                        mma16816(acc[mi*4 + nb*2 + 1], aF[mi], bf1);
                    }
                }
            }
            #pragma unroll
            for (int mi = 0; mi < 5; mi++)
                ldsm4t(aF[mi][0], aF[mi][1], aF[mi][2], aF[mi][3],
                       sAl_b + (uint32_t)((ks + a_k)*KAST + mi*16 + a_m8)*2);
            #pragma unroll
            for (int nb = 0; nb < 2; nb++) {
                uint32_t r0, r1, r2, r3;
                ldsm4t(r0, r1, r2, r3,
                       sBh_b + (uint32_t)((ks + b_k)*KBST + n0w + nb*16 + b_n8)*2);
                uint32_t bf0[2] = {r0, r1}, bf1[2] = {r2, r3};
                #pragma unroll
                for (int mi = 0; mi < 5; mi++) {
                    mma16816(acc[mi*4 + nb*2],     aF[mi], bf0);
                    mma16816(acc[mi*4 + nb*2 + 1], aF[mi], bf1);
                }
            }
        }
    }

    int g = lane >> 2;
    int cl = (lane & 3) * 2;
    size_t base = ((size_t)bh*NSPLIT + sp)*80*R_;
    #pragma unroll
    for (int mi = 0; mi < 5; mi++)
        #pragma unroll
        for (int j = 0; j < 4; j++) {
            int row = mi*16 + g;
            int col = n0w + j*8 + cl;
            *(float2*)(kvp2 + base + (size_t)row*R_ + col) =
                make_float2(acc[mi*4+j][0], acc[mi*4+j][1]);
            *(float2*)(kvp2 + base + (size_t)(row+8)*R_ + col) =
                make_float2(acc[mi*4+j][2], acc[mi*4+j][3]);
        }
}

// ---------------- reduce: sum 16 partials -> kvT hi/lo fp16 [bh][80][256] -------------
__global__ void reduce2_kernel(const float* __restrict__ kvp2,
                               __half* __restrict__ kvth, __half* __restrict__ kvtl) {
    int idx = blockIdx.x*256 + threadIdx.x;
    int bh = idx / (80*R_);
    int rem = idx - bh*(80*R_);
    float s = 0.f;
    #pragma unroll
    for (int sp = 0; sp < NSPLIT; sp++)
        s += kvp2[((size_t)bh*NSPLIT + sp)*80*R_ + rem];
    __half h, l; split_f16(s, h, l);
    size_t o = (size_t)bh*80*R_ + rem;
    kvth[o] = h; kvtl[o] = l;
}

// ---------------- attn via HMMA, single-buffered ----------------
#define ATT_N 80
#define ASM_A (128*AST*2)
#define ASM_B (ATT_N*AST*2)
#define ABUF (2*ASM_A + 2*ASM_B)
__global__ void __launch_bounds__(256) attn_mma(
        const __half* __restrict__ qfh, const __half* __restrict__ qfl,
        const __half* __restrict__ kvth, const __half* __restrict__ kvtl,
        __half* __restrict__ Ch, __half* __restrict__ Cl) {
    extern __shared__ __half sm[];
    uint32_t sbase = smem_u32(sm);
    int t = threadIdx.x, lane = t & 31, w = t >> 5;
    int bh = blockIdx.y, b = bh >> 3, h = bh & 7;
    int s0 = blockIdx.x * 128;

    const __half* Bh_g = kvth + (size_t)bh*ATT_N*R_;
    const __half* Bl_g = kvtl + (size_t)bh*ATT_N*R_;

    float acc[10][4] = {};

    int a_row = w*16 + (lane & 15);
    int a_col8 = (lane >> 4) * 8;
    int b_row = ((lane >> 4) & 1)*8 + (lane & 7);
    int b_col8 = ((lane >> 3) & 1) * 8;

    uint32_t sAh_b = sbase, sAl_b = sbase + ASM_A;
    uint32_t sBh_b = sbase + 2*ASM_A, sBl_b = sbase + 2*ASM_A + ASM_B;

    for (int c = 0; c < 4; c++) {
        #pragma unroll
        for (int j = 0; j < 4; j++) {
            int idx = t + j*256;
            int row = idx >> 3, c8 = idx & 7;
            size_t g = ((size_t)(b*S_ + s0 + row)*H_ + h)*R_ + c*64 + c8*8;
            uint32_t off = (uint32_t)(row*AST + c8*8)*2;
            cpa16(sAh_b + off, qfh + g);
            cpa16(sAl_b + off, qfl + g);
        }
        #pragma unroll
        for (int j = 0; j < 3; j++) {
            int idx = t + j*256;
            if (idx < ATT_N*8) {
                int row = idx >> 3, c8 = idx & 7;
                uint32_t off = (uint32_t)(row*AST + c8*8)*2;
                cpa16(sBh_b + off, Bh_g + row*R_ + c*64 + c8*8);
                cpa16(sBl_b + off, Bl_g + row*R_ + c*64 + c8*8);
            }
        }
        CPA_COMMIT();
        CPA_WAIT(0);
        __syncthreads();

        #pragma unroll
        for (int k16 = 0; k16 < 4; k16++) {
            uint32_t aF[4];
            uint32_t aoff = (uint32_t)(a_row*AST + k16*16 + a_col8)*2;
            ldsm4(aF[0], aF[1], aF[2], aF[3], sAh_b + aoff);
            #pragma unroll
            for (int bs = 0; bs < 2; bs++) {
                uint32_t bBase = bs ? sBl_b : sBh_b;
                #pragma unroll
                for (int p = 0; p < 5; p++) {
                    uint32_t r0, r1, r2, r3;
                    ldsm4(r0, r1, r2, r3,
                          bBase + (uint32_t)((p*16 + b_row)*AST + k16*16 + b_col8)*2);
                    uint32_t bf0[2] = {r0, r1}, bf1[2] = {r2, r3};
                    mma16816(acc[2*p],   aF, bf0);
                    mma16816(acc[2*p+1], aF, bf1);
                }
            }
            ldsm4(aF[0], aF[1], aF[2], aF[3], sAl_b + aoff);
            #pragma unroll
            for (int p = 0; p < 5; p++) {
                uint32_t r0, r1, r2, r3;
                ldsm4(r0, r1, r2, r3,
                      sBh_b + (uint32_t)((p*16 + b_row)*AST + k16*16 + b_col8)*2);
                uint32_t bf0[2] = {r0, r1}, bf1[2] = {r2, r3};
                mma16816(acc[2*p],   aF, bf0);
                mma16816(acc[2*p+1], aF, bf1);
            }
        }
        __syncthreads();
    }

    int g = lane >> 2;
    int cl = (lane & 3) * 2;
    float den0 = __shfl_sync(0xffffffffu, acc[8][0], lane & ~3);
    float den1 = __shfl_sync(0xffffffffu, acc[8][2], lane & ~3);
    float inv0 = 1.0f / (den0 + EPS_);
    float inv1 = 1.0f / (den1 + EPS_);

    size_t srow0 = (size_t)(b*S_ + s0 + w*16 + g);
    #pragma unroll
    for (int nt = 0; nt < 8; nt++) {
        int col = h*KD_ + nt*8 + cl;
        float v0 = acc[nt][0]*inv0, v1 = acc[nt][1]*inv0;
        float v2 = acc[nt][2]*inv1, v3 = acc[nt][3]*inv1;
        __half h0,l0,h1,l1,h2,l2,h3,l3;
        split_f16(v0,h0,l0); split_f16(v1,h1,l1);
        split_f16(v2,h2,l2); split_f16(v3,h3,l3);
        __half2 hp0 = __halves2half2(h0,h1), lp0 = __halves2half2(l0,l1);
        __half2 hp1 = __halves2half2(h2,h3), lp1 = __halves2half2(l2,l3);
        *(uint32_t*)(Ch + srow0*D_ + col)     = *(uint32_t*)&hp0;
        *(uint32_t*)(Cl + srow0*D_ + col)     = *(uint32_t*)&lp0;
        *(uint32_t*)(Ch + (srow0+8)*D_ + col) = *(uint32_t*)&hp1;
        *(uint32_t*)(Cl + (srow0+8)*D_ + col) = *(uint32_t*)&lp1;
    }
}

// ---------------- launch ----------------
extern "C" void kernel_launch(void* const* d_in, const int* in_sizes, int n_in,
                              void* d_out, int out_size) {
    const float* x  = (const float*)d_in[0];
    const float* Wq = (const float*)d_in[1];
    const float* Wk = (const float*)d_in[2];
    const float* Wv = (const float*)d_in[3];
    const float* rf = (const float*)d_in[4];
    const float* Wo = (const float*)d_in[5];
    const float* bo = (const float*)d_in[6];
    float* out = (float*)d_out;

    float *pkvp2;
    __half *pxh, *pxl, *pah, *pal, *pqh, *pql, *pkh, *pkl, *pvh, *pvl;
    __half *prfh, *prfl, *pwh, *pwl, *pqfh, *pqfl, *pkfh, *pkfl, *pkvth, *pkvtl;
    cudaGetSymbolAddress((void**)&pkvp2, g_kvp2);
    cudaGetSymbolAddress((void**)&pxh,   g_xh);
    cudaGetSymbolAddress((void**)&pxl,   g_xl);
    cudaGetSymbolAddress((void**)&pah,   g_ah);
    cudaGetSymbolAddress((void**)&pal,   g_al);
    cudaGetSymbolAddress((void**)&pqh,   g_qh);
    cudaGetSymbolAddress((void**)&pql,   g_ql);
    cudaGetSymbolAddress((void**)&pkh,   g_kh);
    cudaGetSymbolAddress((void**)&pkl,   g_kl);
    cudaGetSymbolAddress((void**)&pvh,   g_vh);
    cudaGetSymbolAddress((void**)&pvl,   g_vl);
    cudaGetSymbolAddress((void**)&prfh,  g_rfh);
    cudaGetSymbolAddress((void**)&prfl,  g_rfl);
    cudaGetSymbolAddress((void**)&pwh,   g_wh);
    cudaGetSymbolAddress((void**)&pwl,   g_wl);
    cudaGetSymbolAddress((void**)&pqfh,  g_qfh);
    cudaGetSymbolAddress((void**)&pqfl,  g_qfl);
    cudaGetSymbolAddress((void**)&pkfh,  g_kfh);
    cudaGetSymbolAddress((void**)&pkfl,  g_kfl);
    cudaGetSymbolAddress((void**)&pkvth, g_kvth);
    cudaGetSymbolAddress((void**)&pkvtl, g_kvtl);

    cudaFuncSetAttribute(qkv_gemm,  cudaFuncAttributeMaxDynamicSharedMemorySize, MMSM);
    cudaFuncSetAttribute(out_gemm,  cudaFuncAttributeMaxDynamicSharedMemorySize, MMSM);
    cudaFuncSetAttribute(feat_mma,  cudaFuncAttributeMaxDynamicSharedMemorySize, FSM_TOT);
    cudaFuncSetAttribute(kvsum_mma, cudaFuncAttributeMaxDynamicSharedMemorySize, KVSM);
    cudaFuncSetAttribute(attn_mma,  cudaFuncAttributeMaxDynamicSharedMemorySize, ABUF);

    const int WSZ = D_*D_;
    wsplit_all<<<dim3(16, 16, 4), dim3(32, 8)>>>(Wq, Wk, Wv, Wo, pwh, pwl);

    split_kernel<<<M_*D_/4/256, 256>>>((const float4*)x, (uint2*)pxh, (uint2*)pxl);
    split_kernel<<<R_*KD_/4/256, 256>>>((const float4*)rf, (uint2*)prfh, (uint2*)prfl);

    qkv_gemm<<<dim3(D_/128, M_/128, 3), 256, MMSM>>>(pxh, pxl, pwh, pwl,
                                                     pqh, pql, pkh, pkl, pvh, pvl);

    feat_mma<<<dim3(ROWS_/128, 2), 256, FSM_TOT>>>(pqh, pql, pkh, pkl, prfh, prfl,
                                                   pqfh, pqfl, pkfh, pkfl);

    kvsum_mma<<<dim3(NSPLIT, B_*H_), 256, KVSM>>>(pvh, pvl, pkfh, pkfl, pkvp2);

    reduce2_kernel<<<B_*H_*80*R_/256, 256>>>(pkvp2, pkvth, pkvtl);

    attn_mma<<<dim3(S_/128, B_*H_), 256, ABUF>>>(pqfh, pqfl, pkvth, pkvtl, pah, pal);

    out_gemm<<<dim3(D_/128, M_/128), 256, MMSM>>>(pah, pal, pwh + 3*WSZ, pwl + 3*WSZ, out, bo);
}

// round 17
// speedup vs baseline: 1.0218x; 1.0218x over previous
#include <cuda_runtime.h>
#include <cuda_bf16.h>
#include <cstdint>
#include <math.h>

#define B_   4
#define S_   4096
#define D_   512
#define H_   8
#define KD_  64
#define R_   256
#define M_   (B_*S_)
#define ROWS_ (M_*H_)
#define EPS_ 1e-3f
#define SCALE_ 0.125f
#define NSPLIT 16

// ---- mma.sync / ldmatrix / cp.async helpers ----
__device__ __forceinline__ uint32_t smem_u32(const void* p) {
    uint32_t a;
    asm("{ .reg .u64 t; cvta.to.shared.u64 t, %1; cvt.u32.u64 %0, t; }" : "=r"(a) : "l"(p));
    return a;
}
__device__ __forceinline__ void ldsm4(uint32_t& r0, uint32_t& r1, uint32_t& r2, uint32_t& r3,
                                      uint32_t addr) {
    asm volatile("ldmatrix.sync.aligned.m8n8.x4.shared.b16 {%0,%1,%2,%3}, [%4];"
                 : "=r"(r0), "=r"(r1), "=r"(r2), "=r"(r3) : "r"(addr));
}
__device__ __forceinline__ void ldsm4t(uint32_t& r0, uint32_t& r1, uint32_t& r2, uint32_t& r3,
                                       uint32_t addr) {
    asm volatile("ldmatrix.sync.aligned.m8n8.x4.trans.shared.b16 {%0,%1,%2,%3}, [%4];"
                 : "=r"(r0), "=r"(r1), "=r"(r2), "=r"(r3) : "r"(addr));
}
__device__ __forceinline__ void mma16816(float* c, const uint32_t* a, const uint32_t* b) {
    asm volatile("mma.sync.aligned.m16n8k16.row.col.f32.bf16.bf16.f32 "
                 "{%0,%1,%2,%3}, {%4,%5,%6,%7}, {%8,%9}, {%0,%1,%2,%3};"
                 : "+f"(c[0]), "+f"(c[1]), "+f"(c[2]), "+f"(c[3])
                 : "r"(a[0]), "r"(a[1]), "r"(a[2]), "r"(a[3]), "r"(b[0]), "r"(b[1]));
}
__device__ __forceinline__ void cpa16(uint32_t dst, const void* src) {
    asm volatile("cp.async.cg.shared.global [%0], [%1], 16;" :: "r"(dst), "l"(src));
}
#define CPA_COMMIT() asm volatile("cp.async.commit_group;" ::: "memory")
#define CPA_WAIT(n)  asm volatile("cp.async.wait_group %0;" :: "n"(n) : "memory")

__device__ __forceinline__ void split_bf16(float v, __nv_bfloat16& h, __nv_bfloat16& l) {
    h = __float2bfloat16(v);
    l = __float2bfloat16(v - __bfloat162float(h));
}

// ---------------- scratch ----------------
__device__ __nv_bfloat16 g_vh[M_*D_];
__device__ __nv_bfloat16 g_vl[M_*D_];
__device__ __nv_bfloat16 g_kfh[(size_t)ROWS_*R_];
__device__ __nv_bfloat16 g_kfl[(size_t)ROWS_*R_];
__device__ float g_kvp2[(size_t)B_*H_*NSPLIT*80*R_];
__device__ __nv_bfloat16 g_qfh[(size_t)ROWS_*R_];
__device__ __nv_bfloat16 g_qfl[(size_t)ROWS_*R_];
__device__ __nv_bfloat16 g_kvth[B_*H_*80*R_];
__device__ __nv_bfloat16 g_kvtl[B_*H_*80*R_];
__device__ __nv_bfloat16 g_xh[M_*D_];
__device__ __nv_bfloat16 g_xl[M_*D_];
__device__ __nv_bfloat16 g_ah[M_*D_];
__device__ __nv_bfloat16 g_al[M_*D_];
__device__ __nv_bfloat16 g_qh[M_*D_];
__device__ __nv_bfloat16 g_ql[M_*D_];
__device__ __nv_bfloat16 g_kh[M_*D_];
__device__ __nv_bfloat16 g_kl[M_*D_];
__device__ __nv_bfloat16 g_rfh[R_*KD_];
__device__ __nv_bfloat16 g_rfl[R_*KD_];
__device__ __nv_bfloat16 g_wh[4][D_*D_];
__device__ __nv_bfloat16 g_wl[4][D_*D_];

// ---------------- fused preprocessing: x split, rf split, all 4 W transpose+split ------
// blocks [0,8192): x split; [8192,8208): rf split; [8208,9232): wsplit (z = idx>>8)
__global__ void prep_all(const float4* __restrict__ x4, const float4* __restrict__ rf4,
                         const float* __restrict__ W0, const float* __restrict__ W1,
                         const float* __restrict__ W2, const float* __restrict__ W3,
                         uint2* __restrict__ xh, uint2* __restrict__ xl,
                         uint2* __restrict__ rfh, uint2* __restrict__ rfl,
                         __nv_bfloat16* __restrict__ Th, __nv_bfloat16* __restrict__ Tl) {
    __shared__ float tile[32][33];
    int bid = blockIdx.x, t = threadIdx.x;
    if (bid < 8192 + 16) {
        const float4* src; uint2 *hi, *lo; int i;
        if (bid < 8192) { src = x4;  hi = xh;  lo = xl;  i = bid*256 + t; }
        else            { src = rf4; hi = rfh; lo = rfl; i = (bid-8192)*256 + t; }
        float4 v = src[i];
        __nv_bfloat16 h0,h1,h2,h3,l0,l1,l2,l3;
        split_bf16(v.x,h0,l0); split_bf16(v.y,h1,l1);
        split_bf16(v.z,h2,l2); split_bf16(v.w,h3,l3);
        __nv_bfloat162 hp0; hp0.x=h0; hp0.y=h1;
        __nv_bfloat162 hp1; hp1.x=h2; hp1.y=h3;
        __nv_bfloat162 lp0; lp0.x=l0; lp0.y=l1;
        __nv_bfloat162 lp1; lp1.x=l2; lp1.y=l3;
        hi[i] = make_uint2(*(uint32_t*)&hp0, *(uint32_t*)&hp1);
        lo[i] = make_uint2(*(uint32_t*)&lp0, *(uint32_t*)&lp1);
    } else {
        int wb = bid - 8208;                // [0, 1024)
        int z = wb >> 8, rem = wb & 255;
        const float* W = (z == 0) ? W0 : (z == 1) ? W1 : (z == 2) ? W2 : W3;
        __nv_bfloat16* th = Th + (size_t)z*D_*D_;
        __nv_bfloat16* tl = Tl + (size_t)z*D_*D_;
        int n0 = (rem & 15)*32, k0 = (rem >> 4)*32;
        int tx = t & 31, ty = t >> 5;       // (32, 8)
        #pragma unroll
        for (int j = 0; j < 32; j += 8)
            tile[ty+j][tx] = W[(size_t)(k0+ty+j)*D_ + n0+tx];
        __syncthreads();
        #pragma unroll
        for (int j = 0; j < 32; j += 8) {
            float v = tile[tx][ty+j];
            __nv_bfloat16 h, l; split_bf16(v, h, l);
            th[(size_t)(n0+ty+j)*D_ + k0+tx] = h;
            tl[(size_t)(n0+ty+j)*D_ + k0+tx] = l;
        }
    }
}

// ============== shared tiling constants ==============
#define AST 72
#define AST2 40
#define T32_BYTES (128*AST2*2)
#define BUF32  (4*T32_BYTES)
#define MMSM (2*BUF32)

// ---------------- fused QKV GEMM: z selects weight + output (all bf16 hi/lo) ----------
__global__ void __launch_bounds__(256, 2) qkv_gemm(
        const __nv_bfloat16* __restrict__ Ah_g, const __nv_bfloat16* __restrict__ Al_g,
        const __nv_bfloat16* __restrict__ Wh_g, const __nv_bfloat16* __restrict__ Wl_g,
        __nv_bfloat16* __restrict__ Qh, __nv_bfloat16* __restrict__ Ql,
        __nv_bfloat16* __restrict__ Kh, __nv_bfloat16* __restrict__ Kl,
        __nv_bfloat16* __restrict__ Vh, __nv_bfloat16* __restrict__ Vl) {
    extern __shared__ __nv_bfloat16 sm[];
    uint32_t sbase = smem_u32(sm);
    int t = threadIdx.x, lane = t & 31, w = t >> 5;
    int wm = w & 3, wn = w >> 2;
    int z = blockIdx.z;
    int n0 = blockIdx.x * 128;
    size_t m0 = (size_t)blockIdx.y * 128;
    const __nv_bfloat16* Bh_g = Wh_g + (size_t)z*D_*D_;
    const __nv_bfloat16* Bl_g = Wl_g + (size_t)z*D_*D_;

    float acc[2][8][4] = {};

    int a_row = wm*32 + (lane & 15);
    int a_col8 = (lane >> 4) * 8;
    int b_row = wn*64 + ((lane >> 4) & 1)*8 + (lane & 7);
    int b_col8 = ((lane >> 3) & 1) * 8;

    int srow[2], sc8[2];
    #pragma unroll
    for (int j = 0; j < 2; j++) { int idx = t + j*256; srow[j] = idx >> 2; sc8[j] = idx & 3; }

    auto stage = [&](int kb, uint32_t bb) {
        #pragma unroll
        for (int j = 0; j < 2; j++) {
            uint32_t off = (uint32_t)(srow[j]*AST2 + sc8[j]*8)*2;
            cpa16(bb + 0*T32_BYTES + off, Ah_g + (m0+srow[j])*D_ + kb + sc8[j]*8);
            cpa16(bb + 1*T32_BYTES + off, Al_g + (m0+srow[j])*D_ + kb + sc8[j]*8);
            cpa16(bb + 2*T32_BYTES + off, Bh_g + (size_t)(n0+srow[j])*D_ + kb + sc8[j]*8);
            cpa16(bb + 3*T32_BYTES + off, Bl_g + (size_t)(n0+srow[j])*D_ + kb + sc8[j]*8);
        }
        CPA_COMMIT();
    };

    stage(0, sbase);
    for (int c = 0; c < 16; c++) {
        int buf = c & 1;
        CPA_WAIT(0);
        __syncthreads();
        if (c < 15) stage((c+1)*32, sbase + (buf^1)*BUF32);

        uint32_t bb = sbase + buf*BUF32;
        uint32_t sAh_b = bb, sAl_b = bb + T32_BYTES;
        uint32_t sBh_b = bb + 2*T32_BYTES, sBl_b = bb + 3*T32_BYTES;

        #pragma unroll
        for (int k16 = 0; k16 < 2; k16++) {
            int ak = k16*16 + a_col8;
            int bk = k16*16 + b_col8;
            uint32_t aF[2][4];
            #pragma unroll
            for (int mt = 0; mt < 2; mt++)
                ldsm4(aF[mt][0], aF[mt][1], aF[mt][2], aF[mt][3],
                      sAh_b + (uint32_t)((a_row + mt*16)*AST2 + ak)*2);
            #pragma unroll
            for (int bs = 0; bs < 2; bs++) {
                uint32_t bBase = bs ? sBl_b : sBh_b;
                uint32_t bF[8][2];
                #pragma unroll
                for (int p = 0; p < 4; p++) {
                    uint32_t r0, r1, r2, r3;
                    ldsm4(r0, r1, r2, r3, bBase + (uint32_t)((b_row + p*16)*AST2 + bk)*2);
                    bF[2*p][0] = r0; bF[2*p][1] = r1;
                    bF[2*p+1][0] = r2; bF[2*p+1][1] = r3;
                }
                #pragma unroll
                for (int mt = 0; mt < 2; mt++)
                    #pragma unroll
                    for (int nt = 0; nt < 8; nt++)
                        mma16816(acc[mt][nt], aF[mt], bF[nt]);
            }
            #pragma unroll
            for (int mt = 0; mt < 2; mt++)
                ldsm4(aF[mt][0], aF[mt][1], aF[mt][2], aF[mt][3],
                      sAl_b + (uint32_t)((a_row + mt*16)*AST2 + ak)*2);
            {
                uint32_t bF[8][2];
                #pragma unroll
                for (int p = 0; p < 4; p++) {
                    uint32_t r0, r1, r2, r3;
                    ldsm4(r0, r1, r2, r3, sBh_b + (uint32_t)((b_row + p*16)*AST2 + bk)*2);
                    bF[2*p][0] = r0; bF[2*p][1] = r1;
                    bF[2*p+1][0] = r2; bF[2*p+1][1] = r3;
                }
                #pragma unroll
                for (int mt = 0; mt < 2; mt++)
                    #pragma unroll
                    for (int nt = 0; nt < 8; nt++)
                        mma16816(acc[mt][nt], aF[mt], bF[nt]);
            }
        }
    }

    int g = lane >> 2;
    int cl = (lane & 3) * 2;
    __nv_bfloat16* Ch = (z == 0) ? Qh : (z == 1) ? Kh : Vh;
    __nv_bfloat16* Cl = (z == 0) ? Ql : (z == 1) ? Kl : Vl;
    #pragma unroll
    for (int mt = 0; mt < 2; mt++)
        #pragma unroll
        for (int nt = 0; nt < 8; nt++) {
            int col = n0 + wn*64 + nt*8 + cl;
            size_t r0 = m0 + wm*32 + mt*16 + g;
            #pragma unroll
            for (int half = 0; half < 2; half++) {
                __nv_bfloat16 hx, lx, hy, ly;
                split_bf16(acc[mt][nt][2*half],   hx, lx);
                split_bf16(acc[mt][nt][2*half+1], hy, ly);
                __nv_bfloat162 hp; hp.x = hx; hp.y = hy;
                __nv_bfloat162 lp; lp.x = lx; lp.y = ly;
                size_t rr = r0 + half*8;
                *(uint32_t*)(Ch + rr*D_ + col) = *(uint32_t*)&hp;
                *(uint32_t*)(Cl + rr*D_ + col) = *(uint32_t*)&lp;
            }
        }
}

// ---------------- final GEMM (fp32 out + bias) ----------------
__global__ void __launch_bounds__(256, 2) out_gemm(
        const __nv_bfloat16* __restrict__ Ah_g, const __nv_bfloat16* __restrict__ Al_g,
        const __nv_bfloat16* __restrict__ Bh_g, const __nv_bfloat16* __restrict__ Bl_g,
        float* __restrict__ C, const float* __restrict__ bias) {
    extern __shared__ __nv_bfloat16 sm[];
    uint32_t sbase = smem_u32(sm);
    int t = threadIdx.x, lane = t & 31, w = t >> 5;
    int wm = w & 3, wn = w >> 2;
    int n0 = blockIdx.x * 128;
    size_t m0 = (size_t)blockIdx.y * 128;

    float acc[2][8][4] = {};

    int a_row = wm*32 + (lane & 15);
    int a_col8 = (lane >> 4) * 8;
    int b_row = wn*64 + ((lane >> 4) & 1)*8 + (lane & 7);
    int b_col8 = ((lane >> 3) & 1) * 8;

    int srow[2], sc8[2];
    #pragma unroll
    for (int j = 0; j < 2; j++) { int idx = t + j*256; srow[j] = idx >> 2; sc8[j] = idx & 3; }

    auto stage = [&](int kb, uint32_t bb) {
        #pragma unroll
        for (int j = 0; j < 2; j++) {
            uint32_t off = (uint32_t)(srow[j]*AST2 + sc8[j]*8)*2;
            cpa16(bb + 0*T32_BYTES + off, Ah_g + (m0+srow[j])*D_ + kb + sc8[j]*8);
            cpa16(bb + 1*T32_BYTES + off, Al_g + (m0+srow[j])*D_ + kb + sc8[j]*8);
            cpa16(bb + 2*T32_BYTES + off, Bh_g + (size_t)(n0+srow[j])*D_ + kb + sc8[j]*8);
            cpa16(bb + 3*T32_BYTES + off, Bl_g + (size_t)(n0+srow[j])*D_ + kb + sc8[j]*8);
        }
        CPA_COMMIT();
    };

    stage(0, sbase);
    for (int c = 0; c < 16; c++) {
        int buf = c & 1;
        CPA_WAIT(0);
        __syncthreads();
        if (c < 15) stage((c+1)*32, sbase + (buf^1)*BUF32);

        uint32_t bb = sbase + buf*BUF32;
        uint32_t sAh_b = bb, sAl_b = bb + T32_BYTES;
        uint32_t sBh_b = bb + 2*T32_BYTES, sBl_b = bb + 3*T32_BYTES;

        #pragma unroll
        for (int k16 = 0; k16 < 2; k16++) {
            int ak = k16*16 + a_col8;
            int bk = k16*16 + b_col8;
            uint32_t aF[2][4];
            #pragma unroll
            for (int mt = 0; mt < 2; mt++)
                ldsm4(aF[mt][0], aF[mt][1], aF[mt][2], aF[mt][3],
                      sAh_b + (uint32_t)((a_row + mt*16)*AST2 + ak)*2);
            #pragma unroll
            for (int bs = 0; bs < 2; bs++) {
                uint32_t bBase = bs ? sBl_b : sBh_b;
                uint32_t bF[8][2];
                #pragma unroll
                for (int p = 0; p < 4; p++) {
                    uint32_t r0, r1, r2, r3;
                    ldsm4(r0, r1, r2, r3, bBase + (uint32_t)((b_row + p*16)*AST2 + bk)*2);
                    bF[2*p][0] = r0; bF[2*p][1] = r1;
                    bF[2*p+1][0] = r2; bF[2*p+1][1] = r3;
                }
                #pragma unroll
                for (int mt = 0; mt < 2; mt++)
                    #pragma unroll
                    for (int nt = 0; nt < 8; nt++)
                        mma16816(acc[mt][nt], aF[mt], bF[nt]);
            }
            #pragma unroll
            for (int mt = 0; mt < 2; mt++)
                ldsm4(aF[mt][0], aF[mt][1], aF[mt][2], aF[mt][3],
                      sAl_b + (uint32_t)((a_row + mt*16)*AST2 + ak)*2);
            {
                uint32_t bF[8][2];
                #pragma unroll
                for (int p = 0; p < 4; p++) {
                    uint32_t r0, r1, r2, r3;
                    ldsm4(r0, r1, r2, r3, sBh_b + (uint32_t)((b_row + p*16)*AST2 + bk)*2);
                    bF[2*p][0] = r0; bF[2*p][1] = r1;
                    bF[2*p+1][0] = r2; bF[2*p+1][1] = r3;
                }
                #pragma unroll
                for (int mt = 0; mt < 2; mt++)
                    #pragma unroll
                    for (int nt = 0; nt < 8; nt++)
                        mma16816(acc[mt][nt], aF[mt], bF[nt]);
            }
        }
    }

    int g = lane >> 2;
    int cl = (lane & 3) * 2;
    #pragma unroll
    for (int mt = 0; mt < 2; mt++) {
        #pragma unroll
        for (int nt = 0; nt < 8; nt++) {
            int col = n0 + wn*64 + nt*8 + cl;
            size_t r0 = m0 + wm*32 + mt*16 + g;
            float bx = bias[col], by = bias[col+1];
            *(float2*)(C + r0*D_ + col)       = make_float2(acc[mt][nt][0] + bx, acc[mt][nt][1] + by);
            *(float2*)(C + (r0 + 8)*D_ + col) = make_float2(acc[mt][nt][2] + bx, acc[mt][nt][3] + by);
        }
    }
}

// ---------------- fused feat via HMMA: z=0 -> qf, z=1 -> kf (bf16 hi/lo out) ----------
#define FSM_A (128*AST*2)
#define FSM_B (256*AST*2)
#define FSM_TOT (2*FSM_A + 2*FSM_B)
__global__ void __launch_bounds__(256) feat_mma(
        const __nv_bfloat16* __restrict__ qh, const __nv_bfloat16* __restrict__ ql,
        const __nv_bfloat16* __restrict__ kh, const __nv_bfloat16* __restrict__ kl,
        const __nv_bfloat16* __restrict__ rfh, const __nv_bfloat16* __restrict__ rfl,
        __nv_bfloat16* __restrict__ qfh, __nv_bfloat16* __restrict__ qfl,
        __nv_bfloat16* __restrict__ kfh, __nv_bfloat16* __restrict__ kfl) {
    extern __shared__ __nv_bfloat16 sm[];
    uint32_t sbase = smem_u32(sm);
    uint32_t sAh_b = sbase, sAl_b = sbase + FSM_A;
    uint32_t sBh_b = sbase + 2*FSM_A, sBl_b = sbase + 2*FSM_A + FSM_B;
    int t = threadIdx.x, lane = t & 31, w = t >> 5;
    int z = blockIdx.y;
    const __nv_bfloat16* Ah_g = z ? kh : qh;
    const __nv_bfloat16* Al_g = z ? kl : ql;
    __nv_bfloat16* outH = z ? kfh : qfh;
    __nv_bfloat16* outL = z ? kfl : qfl;
    size_t m0 = (size_t)blockIdx.x * 128;

    #pragma unroll
    for (int j = 0; j < 4; j++) {
        int idx = t + j*256;
        int row = idx >> 3, c8 = idx & 7;
        uint32_t off = (uint32_t)(row*AST + c8*8)*2;
        cpa16(sAh_b + off, Ah_g + (m0+row)*KD_ + c8*8);
        cpa16(sAl_b + off, Al_g + (m0+row)*KD_ + c8*8);
    }
    #pragma unroll
    for (int j = 0; j < 8; j++) {
        int idx = t + j*256;
        int row = idx >> 3, c8 = idx & 7;
        uint32_t off = (uint32_t)(row*AST + c8*8)*2;
        cpa16(sBh_b + off, rfh + row*KD_ + c8*8);
        cpa16(sBl_b + off, rfl + row*KD_ + c8*8);
    }
    CPA_COMMIT();
    CPA_WAIT(0);
    __syncthreads();

    float acc[32][4] = {};
    int a_row = w*16 + (lane & 15);
    int a_col8 = (lane >> 4) * 8;
    int b_row = ((lane >> 4) & 1)*8 + (lane & 7);
    int b_col8 = ((lane >> 3) & 1) * 8;

    #pragma unroll
    for (int k16 = 0; k16 < 4; k16++) {
        uint32_t aF[4];
        uint32_t aoff = (uint32_t)(a_row*AST + k16*16 + a_col8)*2;
        ldsm4(aF[0], aF[1], aF[2], aF[3], sAh_b + aoff);
        #pragma unroll
        for (int bs = 0; bs < 2; bs++) {
            uint32_t bBase = bs ? sBl_b : sBh_b;
            #pragma unroll
            for (int p = 0; p < 16; p++) {
                uint32_t r0, r1, r2, r3;
                ldsm4(r0, r1, r2, r3,
                      bBase + (uint32_t)((p*16 + b_row)*AST + k16*16 + b_col8)*2);
                uint32_t bf0[2] = {r0, r1}, bf1[2] = {r2, r3};
                mma16816(acc[2*p],   aF, bf0);
                mma16816(acc[2*p+1], aF, bf1);
            }
        }
        ldsm4(aF[0], aF[1], aF[2], aF[3], sAl_b + aoff);
        #pragma unroll
        for (int p = 0; p < 16; p++) {
            uint32_t r0, r1, r2, r3;
            ldsm4(r0, r1, r2, r3,
                  sBh_b + (uint32_t)((p*16 + b_row)*AST + k16*16 + b_col8)*2);
            uint32_t bf0[2] = {r0, r1}, bf1[2] = {r2, r3};
            mma16816(acc[2*p],   aF, bf0);
            mma16816(acc[2*p+1], aF, bf1);
        }
    }

    int g = lane >> 2;
    float mx0 = -1e30f, mx1 = -1e30f;
    #pragma unroll
    for (int nt = 0; nt < 32; nt++) {
        acc[nt][0] *= SCALE_; acc[nt][1] *= SCALE_;
        acc[nt][2] *= SCALE_; acc[nt][3] *= SCALE_;
        mx0 = fmaxf(mx0, fmaxf(acc[nt][0], acc[nt][1]));
        mx1 = fmaxf(mx1, fmaxf(acc[nt][2], acc[nt][3]));
    }
    mx0 = fmaxf(mx0, __shfl_xor_sync(0xffffffffu, mx0, 1));
    mx0 = fmaxf(mx0, __shfl_xor_sync(0xffffffffu, mx0, 2));
    mx1 = fmaxf(mx1, __shfl_xor_sync(0xffffffffu, mx1, 1));
    mx1 = fmaxf(mx1, __shfl_xor_sync(0xffffffffu, mx1, 2));

    size_t row0 = m0 + w*16 + g;
    int cl = (lane & 3) * 2;
    #pragma unroll
    for (int nt = 0; nt < 32; nt++) {
        int col = nt*8 + cl;
        float v0 = __expf(acc[nt][0]-mx0)+EPS_, v1 = __expf(acc[nt][1]-mx0)+EPS_;
        float v2 = __expf(acc[nt][2]-mx1)+EPS_, v3 = __expf(acc[nt][3]-mx1)+EPS_;
        __nv_bfloat16 h0,l0,h1,l1,h2,l2,h3,l3;
        split_bf16(v0,h0,l0); split_bf16(v1,h1,l1);
        split_bf16(v2,h2,l2); split_bf16(v3,h3,l3);
        __nv_bfloat162 hp0; hp0.x=h0; hp0.y=h1;
        __nv_bfloat162 lp0; lp0.x=l0; lp0.y=l1;
        __nv_bfloat162 hp1; hp1.x=h2; hp1.y=h3;
        __nv_bfloat162 lp1; lp1.x=l2; lp1.y=l3;
        *(uint32_t*)(outH + row0*R_ + col)     = *(uint32_t*)&hp0;
        *(uint32_t*)(outL + row0*R_ + col)     = *(uint32_t*)&lp0;
        *(uint32_t*)(outH + (row0+8)*R_ + col) = *(uint32_t*)&hp1;
        *(uint32_t*)(outL + (row0+8)*R_ + col) = *(uint32_t*)&lp1;
    }
}

// ---------------- kvsum via HMMA (trans ldmatrix): partials [bh][sp][80][256] ---------
#define KAST 88
#define KBST 264
#define KVS_A_T (32*KAST*2)
#define KVS_B_T (32*KBST*2)
#define KVS_BUF (2*KVS_A_T + 2*KVS_B_T)
#define KVSM (2*KVS_BUF)
__global__ void __launch_bounds__(256, 2) kvsum_mma(
        const __nv_bfloat16* __restrict__ vh, const __nv_bfloat16* __restrict__ vl,
        const __nv_bfloat16* __restrict__ kfh, const __nv_bfloat16* __restrict__ kfl,
        float* __restrict__ kvp2) {
    extern __shared__ __nv_bfloat16 sm[];
    uint32_t sbase = smem_u32(sm);
    int t = threadIdx.x, lane = t & 31, w = t >> 5;
    int sp = blockIdx.x, bh = blockIdx.y;
    int b = bh >> 3, h = bh & 7;
    int sb0 = sp * 256;

    for (int i = t; i < 512; i += 256) {
        int row = i >> 4, c = 64 + (i & 15);
        __nv_bfloat16 hv = (c == 64) ? __float2bfloat16(1.0f) : __float2bfloat16(0.0f);
        __nv_bfloat16 zv = __float2bfloat16(0.0f);
        #pragma unroll
        for (int bu = 0; bu < 2; bu++) {
            sm[(bu*KVS_BUF)/2 + row*KAST + c] = hv;
            sm[(bu*KVS_BUF + KVS_A_T)/2 + row*KAST + c] = zv;
        }
    }

    float acc[20][4] = {};
    int n0w = w * 32;

    auto stage = [&](int c, uint32_t bb) {
        int srow = t >> 3, sc8 = t & 7;
        size_t vs = (size_t)(b*S_ + sb0 + c*32 + srow)*D_ + h*KD_ + sc8*8;
        uint32_t aoff = (uint32_t)(srow*KAST + sc8*8)*2;
        cpa16(bb + aoff,           vh + vs);
        cpa16(bb + KVS_A_T + aoff, vl + vs);
        #pragma unroll
        for (int j = 0; j < 4; j++) {
            int idx = t + j*256;
            int row = idx >> 5, c8 = idx & 31;
            size_t ks = ((size_t)(b*S_ + sb0 + c*32 + row)*H_ + h)*R_ + c8*8;
            uint32_t boff = (uint32_t)(row*KBST + c8*8)*2;
            cpa16(bb + 2*KVS_A_T + boff,           kfh + ks);
            cpa16(bb + 2*KVS_A_T + KVS_B_T + boff, kfl + ks);
        }
        CPA_COMMIT();
    };

    stage(0, sbase);
    for (int c = 0; c < 8; c++) {
        int buf = c & 1;
        CPA_WAIT(0);
        __syncthreads();
        if (c < 7) stage(c+1, sbase + (buf^1)*KVS_BUF);

        uint32_t bb = sbase + buf*KVS_BUF;
        uint32_t sAh_b = bb, sAl_b = bb + KVS_A_T;
        uint32_t sBh_b = bb + 2*KVS_A_T, sBl_b = bb + 2*KVS_A_T + KVS_B_T;

        int a_k = ((lane >> 4) & 1)*8 + (lane & 7);
        int a_m8 = ((lane >> 3) & 1)*8;
        int b_k = ((lane >> 3) & 1)*8 + (lane & 7);
        int b_n8 = ((lane >> 4) & 1)*8;

        #pragma unroll
        for (int k16 = 0; k16 < 2; k16++) {
            int ks = k16*16;
            uint32_t aF[5][4];
            #pragma unroll
            for (int mi = 0; mi < 5; mi++)
                ldsm4t(aF[mi][0], aF[mi][1], aF[mi][2], aF[mi][3],
                       sAh_b + (uint32_t)((ks + a_k)*KAST + mi*16 + a_m8)*2);
            #pragma unroll
            for (int bs = 0; bs < 2; bs++) {
                uint32_t bBase = bs ? sBl_b : sBh_b;
                #pragma unroll
                for (int nb = 0; nb < 2; nb++) {
                    uint32_t r0, r1, r2, r3;
                    ldsm4t(r0, r1, r2, r3,
                           bBase + (uint32_t)((ks + b_k)*KBST + n0w + nb*16 + b_n8)*2);
                    uint32_t bf0[2] = {r0, r1}, bf1[2] = {r2, r3};
                    #pragma unroll
                    for (int mi = 0; mi < 5; mi++) {
                        mma16816(acc[mi*4 + nb*2],     aF[mi], bf0);
                        mma16816(acc[mi*4 + nb*2 + 1], aF[mi], bf1);
                    }
                }
            }
            #pragma unroll
            for (int mi = 0; mi < 5; mi++)
                ldsm4t(aF[mi][0], aF[mi][1], aF[mi][2], aF[mi][3],
                       sAl_b + (uint32_t)((ks + a_k)*KAST + mi*16 + a_m8)*2);
            #pragma unroll
            for (int nb = 0; nb < 2; nb++) {
                uint32_t r0, r1, r2, r3;
                ldsm4t(r0, r1, r2, r3,
                       sBh_b + (uint32_t)((ks + b_k)*KBST + n0w + nb*16 + b_n8)*2);
                uint32_t bf0[2] = {r0, r1}, bf1[2] = {r2, r3};
                #pragma unroll
                for (int mi = 0; mi < 5; mi++) {
                    mma16816(acc[mi*4 + nb*2],     aF[mi], bf0);
                    mma16816(acc[mi*4 + nb*2 + 1], aF[mi], bf1);
                }
            }
        }
    }

    int g = lane >> 2;
    int cl = (lane & 3) * 2;
    size_t base = ((size_t)bh*NSPLIT + sp)*80*R_;
    #pragma unroll
    for (int mi = 0; mi < 5; mi++)
        #pragma unroll
        for (int j = 0; j < 4; j++) {
            int row = mi*16 + g;
            int col = n0w + j*8 + cl;
            *(float2*)(kvp2 + base + (size_t)row*R_ + col) =
                make_float2(acc[mi*4+j][0], acc[mi*4+j][1]);
            *(float2*)(kvp2 + base + (size_t)(row+8)*R_ + col) =
                make_float2(acc[mi*4+j][2], acc[mi*4+j][3]);
        }
}

// ---------------- reduce: sum 16 partials -> kvT hi/lo bf16 [bh][80][256] -------------
__global__ void reduce2_kernel(const float* __restrict__ kvp2,
                               __nv_bfloat16* __restrict__ kvth, __nv_bfloat16* __restrict__ kvtl) {
    int idx = blockIdx.x*256 + threadIdx.x;
    int bh = idx / (80*R_);
    int rem = idx - bh*(80*R_);
    float s = 0.f;
    #pragma unroll
    for (int sp = 0; sp < NSPLIT; sp++)
        s += kvp2[((size_t)bh*NSPLIT + sp)*80*R_ + rem];
    __nv_bfloat16 h, l; split_bf16(s, h, l);
    size_t o = (size_t)bh*80*R_ + rem;
    kvth[o] = h; kvtl[o] = l;
}

// ---------------- attn via HMMA, single-buffered ----------------
#define ATT_N 80
#define ASM_A (128*AST*2)
#define ASM_B (ATT_N*AST*2)
#define ABUF (2*ASM_A + 2*ASM_B)
__global__ void __launch_bounds__(256) attn_mma(
        const __nv_bfloat16* __restrict__ qfh, const __nv_bfloat16* __restrict__ qfl,
        const __nv_bfloat16* __restrict__ kvth, const __nv_bfloat16* __restrict__ kvtl,
        __nv_bfloat16* __restrict__ Ch, __nv_bfloat16* __restrict__ Cl) {
    extern __shared__ __nv_bfloat16 sm[];
    uint32_t sbase = smem_u32(sm);
    int t = threadIdx.x, lane = t & 31, w = t >> 5;
    int bh = blockIdx.y, b = bh >> 3, h = bh & 7;
    int s0 = blockIdx.x * 128;

    const __nv_bfloat16* Bh_g = kvth + (size_t)bh*ATT_N*R_;
    const __nv_bfloat16* Bl_g = kvtl + (size_t)bh*ATT_N*R_;

    float acc[10][4] = {};

    int a_row = w*16 + (lane & 15);
    int a_col8 = (lane >> 4) * 8;
    int b_row = ((lane >> 4) & 1)*8 + (lane & 7);
    int b_col8 = ((lane >> 3) & 1) * 8;

    uint32_t sAh_b = sbase, sAl_b = sbase + ASM_A;
    uint32_t sBh_b = sbase + 2*ASM_A, sBl_b = sbase + 2*ASM_A + ASM_B;

    for (int c = 0; c < 4; c++) {
        #pragma unroll
        for (int j = 0; j < 4; j++) {
            int idx = t + j*256;
            int row = idx >> 3, c8 = idx & 7;
            size_t g = ((size_t)(b*S_ + s0 + row)*H_ + h)*R_ + c*64 + c8*8;
            uint32_t off = (uint32_t)(row*AST + c8*8)*2;
            cpa16(sAh_b + off, qfh + g);
            cpa16(sAl_b + off, qfl + g);
        }
        #pragma unroll
        for (int j = 0; j < 3; j++) {
            int idx = t + j*256;
            if (idx < ATT_N*8) {
                int row = idx >> 3, c8 = idx & 7;
                uint32_t off = (uint32_t)(row*AST + c8*8)*2;
                cpa16(sBh_b + off, Bh_g + row*R_ + c*64 + c8*8);
                cpa16(sBl_b + off, Bl_g + row*R_ + c*64 + c8*8);
            }
        }
        CPA_COMMIT();
        CPA_WAIT(0);
        __syncthreads();

        #pragma unroll
        for (int k16 = 0; k16 < 4; k16++) {
            uint32_t aF[4];
            uint32_t aoff = (uint32_t)(a_row*AST + k16*16 + a_col8)*2;
            ldsm4(aF[0], aF[1], aF[2], aF[3], sAh_b + aoff);
            #pragma unroll
            for (int bs = 0; bs < 2; bs++) {
                uint32_t bBase = bs ? sBl_b : sBh_b;
                #pragma unroll
                for (int p = 0; p < 5; p++) {
                    uint32_t r0, r1, r2, r3;
                    ldsm4(r0, r1, r2, r3,
                          bBase + (uint32_t)((p*16 + b_row)*AST + k16*16 + b_col8)*2);
                    uint32_t bf0[2] = {r0, r1}, bf1[2] = {r2, r3};
                    mma16816(acc[2*p],   aF, bf0);
                    mma16816(acc[2*p+1], aF, bf1);
                }
            }
            ldsm4(aF[0], aF[1], aF[2], aF[3], sAl_b + aoff);
            #pragma unroll
            for (int p = 0; p < 5; p++) {
                uint32_t r0, r1, r2, r3;
                ldsm4(r0, r1, r2, r3,
                      sBh_b + (uint32_t)((p*16 + b_row)*AST + k16*16 + b_col8)*2);
                uint32_t bf0[2] = {r0, r1}, bf1[2] = {r2, r3};
                mma16816(acc[2*p],   aF, bf0);
                mma16816(acc[2*p+1], aF, bf1);
            }
        }
        __syncthreads();
    }

    int g = lane >> 2;
    int cl = (lane & 3) * 2;
    float den0 = __shfl_sync(0xffffffffu, acc[8][0], lane & ~3);
    float den1 = __shfl_sync(0xffffffffu, acc[8][2], lane & ~3);
    float inv0 = 1.0f / (den0 + EPS_);
    float inv1 = 1.0f / (den1 + EPS_);

    size_t srow0 = (size_t)(b*S_ + s0 + w*16 + g);
    #pragma unroll
    for (int nt = 0; nt < 8; nt++) {
        int col = h*KD_ + nt*8 + cl;
        float v0 = acc[nt][0]*inv0, v1 = acc[nt][1]*inv0;
        float v2 = acc[nt][2]*inv1, v3 = acc[nt][3]*inv1;
        __nv_bfloat16 h0,l0,h1,l1,h2,l2,h3,l3;
        split_bf16(v0,h0,l0); split_bf16(v1,h1,l1);
        split_bf16(v2,h2,l2); split_bf16(v3,h3,l3);
        __nv_bfloat162 hp0; hp0.x=h0; hp0.y=h1;
        __nv_bfloat162 lp0; lp0.x=l0; lp0.y=l1;
        __nv_bfloat162 hp1; hp1.x=h2; hp1.y=h3;
        __nv_bfloat162 lp1; lp1.x=l2; lp1.y=l3;
        *(uint32_t*)(Ch + srow0*D_ + col)     = *(uint32_t*)&hp0;
        *(uint32_t*)(Cl + srow0*D_ + col)     = *(uint32_t*)&lp0;
        *(uint32_t*)(Ch + (srow0+8)*D_ + col) = *(uint32_t*)&hp1;
        *(uint32_t*)(Cl + (srow0+8)*D_ + col) = *(uint32_t*)&lp1;
    }
}

// ---------------- launch ----------------
extern "C" void kernel_launch(void* const* d_in, const int* in_sizes, int n_in,
                              void* d_out, int out_size) {
    const float* x  = (const float*)d_in[0];
    const float* Wq = (const float*)d_in[1];
    const float* Wk = (const float*)d_in[2];
    const float* Wv = (const float*)d_in[3];
    const float* rf = (const float*)d_in[4];
    const float* Wo = (const float*)d_in[5];
    const float* bo = (const float*)d_in[6];
    float* out = (float*)d_out;

    float *pkvp2;
    __nv_bfloat16 *pxh, *pxl, *pah, *pal, *pqh, *pql, *pkh, *pkl, *pvh, *pvl;
    __nv_bfloat16 *prfh, *prfl, *pwh, *pwl, *pqfh, *pqfl, *pkfh, *pkfl, *pkvth, *pkvtl;
    cudaGetSymbolAddress((void**)&pkvp2, g_kvp2);
    cudaGetSymbolAddress((void**)&pxh,   g_xh);
    cudaGetSymbolAddress((void**)&pxl,   g_xl);
    cudaGetSymbolAddress((void**)&pah,   g_ah);
    cudaGetSymbolAddress((void**)&pal,   g_al);
    cudaGetSymbolAddress((void**)&pqh,   g_qh);
    cudaGetSymbolAddress((void**)&pql,   g_ql);
    cudaGetSymbolAddress((void**)&pkh,   g_kh);
    cudaGetSymbolAddress((void**)&pkl,   g_kl);
    cudaGetSymbolAddress((void**)&pvh,   g_vh);
    cudaGetSymbolAddress((void**)&pvl,   g_vl);
    cudaGetSymbolAddress((void**)&prfh,  g_rfh);
    cudaGetSymbolAddress((void**)&prfl,  g_rfl);
    cudaGetSymbolAddress((void**)&pwh,   g_wh);
    cudaGetSymbolAddress((void**)&pwl,   g_wl);
    cudaGetSymbolAddress((void**)&pqfh,  g_qfh);
    cudaGetSymbolAddress((void**)&pqfl,  g_qfl);
    cudaGetSymbolAddress((void**)&pkfh,  g_kfh);
    cudaGetSymbolAddress((void**)&pkfl,  g_kfl);
    cudaGetSymbolAddress((void**)&pkvth, g_kvth);
    cudaGetSymbolAddress((void**)&pkvtl, g_kvtl);

    cudaFuncSetAttribute(qkv_gemm,  cudaFuncAttributeMaxDynamicSharedMemorySize, MMSM);
    cudaFuncSetAttribute(out_gemm,  cudaFuncAttributeMaxDynamicSharedMemorySize, MMSM);
    cudaFuncSetAttribute(feat_mma,  cudaFuncAttributeMaxDynamicSharedMemorySize, FSM_TOT);
    cudaFuncSetAttribute(kvsum_mma, cudaFuncAttributeMaxDynamicSharedMemorySize, KVSM);
    cudaFuncSetAttribute(attn_mma,  cudaFuncAttributeMaxDynamicSharedMemorySize, ABUF);

    const int WSZ = D_*D_;

    // fused preprocessing: x split (8192 blocks) + rf split (16) + 4x wsplit (1024)
    prep_all<<<8192 + 16 + 1024, 256>>>((const float4*)x, (const float4*)rf,
                                        Wq, Wk, Wv, Wo,
                                        (uint2*)pxh, (uint2*)pxl,
                                        (uint2*)prfh, (uint2*)prfl,
                                        pwh, pwl);

    qkv_gemm<<<dim3(D_/128, M_/128, 3), 256, MMSM>>>(pxh, pxl, pwh, pwl,
                                                     pqh, pql, pkh, pkl, pvh, pvl);

    feat_mma<<<dim3(ROWS_/128, 2), 256, FSM_TOT>>>(pqh, pql, pkh, pkl, prfh, prfl,
                                                   pqfh, pqfl, pkfh, pkfl);

    kvsum_mma<<<dim3(NSPLIT, B_*H_), 256, KVSM>>>(pvh, pvl, pkfh, pkfl, pkvp2);

    reduce2_kernel<<<B_*H_*80*R_/256, 256>>>(pkvp2, pkvth, pkvtl);

    attn_mma<<<dim3(S_/128, B_*H_), 256, ABUF>>>(pqfh, pqfl, pkvth, pkvtl, pah, pal);

    out_gemm<<<dim3(D_/128, M_/128), 256, MMSM>>>(pah, pal, pwh + 3*WSZ, pwl + 3*WSZ, out, bo);
}